// round 1
// baseline (speedup 1.0000x reference)
#include <cuda_runtime.h>
#include <cuda_bf16.h>
#include <math.h>

// LSTM cell: BATCH=4096, IN=HID=1024.
// Stage 1: 4 gate pre-activation GEMMs (each K=2048: input@Wi^T + h@Wh^T) -> scratch
// Stage 2: elementwise epilogue (biases, sigmoid/tanh, cell update) -> out = [h' ; c']

#define BATCH_N 4096
#define HID_N   1024
#define GATE_ELEMS ((size_t)BATCH_N * HID_N)

// 64 MB scratch for the 4 gate pre-activations (device global: no allocation APIs)
__device__ float g_gates[4 * GATE_ELEMS];

struct GateW {
    const float* wi[4];
    const float* wh[4];
};

#define BM 128
#define BN 128
#define BK 8
#define PAD 4

__global__ __launch_bounds__(256)
void gemm_gates_kernel(const float* __restrict__ input,
                       const float* __restrict__ hstate,
                       GateW P)
{
    __shared__ __align__(16) float As[BK][BM + PAD];
    __shared__ __align__(16) float Bs[BK][BN + PAD];

    const int gate = blockIdx.z;
    const float* W1 = P.wi[gate];   // [HID, IN] row-major, out[b,j] = sum_k A[b,k]*W[j,k]
    const float* W2 = P.wh[gate];

    const int row0 = blockIdx.y * BM;   // batch dim
    const int col0 = blockIdx.x * BN;   // hidden (j) dim

    const int tid = threadIdx.x;
    const int tx = tid % 16;            // 16 x 8 = 128 cols
    const int ty = tid / 16;            // 16 x 8 = 128 rows

    // global-load mapping: one float4 of A and one of W per thread per k-tile
    const int lr = tid / 2;             // 0..127 (row within tile)
    const int lc = (tid % 2) * 4;       // 0 or 4 (col within 8-wide k-tile)

    float acc[8][8];
#pragma unroll
    for (int i = 0; i < 8; i++)
#pragma unroll
        for (int j = 0; j < 8; j++) acc[i][j] = 0.0f;

    const int NKT = HID_N / BK;         // 128 k-tiles per operand
    for (int kt = 0; kt < 2 * NKT; kt++) {
        const bool first = (kt < NKT);
        const float* A = first ? input : hstate;
        const float* W = first ? W1 : W2;
        const int k0 = (first ? kt : kt - NKT) * BK;

        const float4 av = *reinterpret_cast<const float4*>(
            &A[(size_t)(row0 + lr) * HID_N + k0 + lc]);
        const float4 wv = *reinterpret_cast<const float4*>(
            &W[(size_t)(col0 + lr) * HID_N + k0 + lc]);

        As[lc + 0][lr] = av.x; As[lc + 1][lr] = av.y;
        As[lc + 2][lr] = av.z; As[lc + 3][lr] = av.w;
        Bs[lc + 0][lr] = wv.x; Bs[lc + 1][lr] = wv.y;
        Bs[lc + 2][lr] = wv.z; Bs[lc + 3][lr] = wv.w;
        __syncthreads();

#pragma unroll
        for (int kk = 0; kk < BK; kk++) {
            float a_frag[8], b_frag[8];
            float4 a0 = *reinterpret_cast<const float4*>(&As[kk][ty * 8]);
            float4 a1 = *reinterpret_cast<const float4*>(&As[kk][ty * 8 + 4]);
            float4 b0 = *reinterpret_cast<const float4*>(&Bs[kk][tx * 8]);
            float4 b1 = *reinterpret_cast<const float4*>(&Bs[kk][tx * 8 + 4]);
            a_frag[0] = a0.x; a_frag[1] = a0.y; a_frag[2] = a0.z; a_frag[3] = a0.w;
            a_frag[4] = a1.x; a_frag[5] = a1.y; a_frag[6] = a1.z; a_frag[7] = a1.w;
            b_frag[0] = b0.x; b_frag[1] = b0.y; b_frag[2] = b0.z; b_frag[3] = b0.w;
            b_frag[4] = b1.x; b_frag[5] = b1.y; b_frag[6] = b1.z; b_frag[7] = b1.w;
#pragma unroll
            for (int i = 0; i < 8; i++)
#pragma unroll
                for (int j = 0; j < 8; j++)
                    acc[i][j] = fmaf(a_frag[i], b_frag[j], acc[i][j]);
        }
        __syncthreads();
    }

    float* out = &g_gates[(size_t)gate * GATE_ELEMS];
#pragma unroll
    for (int i = 0; i < 8; i++) {
        const int r = row0 + ty * 8 + i;
#pragma unroll
        for (int j = 0; j < 8; j += 4) {
            float4 v = make_float4(acc[i][j], acc[i][j + 1], acc[i][j + 2], acc[i][j + 3]);
            *reinterpret_cast<float4*>(&out[(size_t)r * HID_N + col0 + tx * 8 + j]) = v;
        }
    }
}

__device__ __forceinline__ float sigmoid_f(float x) {
    return 1.0f / (1.0f + expf(-x));
}

__global__ __launch_bounds__(256)
void lstm_epilogue_kernel(const float* __restrict__ c,
                          const float* __restrict__ b_ii, const float* __restrict__ b_ih,
                          const float* __restrict__ b_fi, const float* __restrict__ b_fh,
                          const float* __restrict__ b_gi, const float* __restrict__ b_gh,
                          const float* __restrict__ b_oi, const float* __restrict__ b_oh,
                          float* __restrict__ out)
{
    const size_t idx = (size_t)blockIdx.x * blockDim.x + threadIdx.x;
    if (idx >= GATE_ELEMS) return;
    const int j = (int)(idx & (HID_N - 1));

    float xi = g_gates[idx]                 + b_ii[j] + b_ih[j];
    float xf = g_gates[idx + GATE_ELEMS]    + b_fi[j] + b_fh[j];
    float xg = g_gates[idx + 2 * GATE_ELEMS] + b_gi[j] + b_gh[j];
    float xo = g_gates[idx + 3 * GATE_ELEMS] + b_oi[j] + b_oh[j];

    float gi = sigmoid_f(xi);
    float gf = sigmoid_f(xf);
    float gg = tanhf(xg);
    float go = sigmoid_f(xo);

    float cp = gf * c[idx] + gi * gg;
    float hp = go * tanhf(cp);

    out[idx] = hp;                 // h'
    out[idx + GATE_ELEMS] = cp;    // c'
}

extern "C" void kernel_launch(void* const* d_in, const int* in_sizes, int n_in,
                              void* d_out, int out_size)
{
    // metadata order:
    // 0 input, 1 h, 2 c,
    // 3 w_i_i, 4 b_i_i, 5 w_i_h, 6 b_i_h,
    // 7 w_f_i, 8 b_f_i, 9 w_f_h, 10 b_f_h,
    // 11 w_g_i, 12 b_g_i, 13 w_g_h, 14 b_g_h,
    // 15 w_o_i, 16 b_o_i, 17 w_o_h, 18 b_o_h
    const float* input = (const float*)d_in[0];
    const float* h     = (const float*)d_in[1];
    const float* c     = (const float*)d_in[2];

    GateW P;
    P.wi[0] = (const float*)d_in[3];  P.wh[0] = (const float*)d_in[5];   // i
    P.wi[1] = (const float*)d_in[7];  P.wh[1] = (const float*)d_in[9];   // f
    P.wi[2] = (const float*)d_in[11]; P.wh[2] = (const float*)d_in[13];  // g
    P.wi[3] = (const float*)d_in[15]; P.wh[3] = (const float*)d_in[17];  // o

    const float* b_ii = (const float*)d_in[4];
    const float* b_ih = (const float*)d_in[6];
    const float* b_fi = (const float*)d_in[8];
    const float* b_fh = (const float*)d_in[10];
    const float* b_gi = (const float*)d_in[12];
    const float* b_gh = (const float*)d_in[14];
    const float* b_oi = (const float*)d_in[16];
    const float* b_oh = (const float*)d_in[18];

    float* out = (float*)d_out;

    dim3 grid(HID_N / BN, BATCH_N / BM, 4);   // (8, 32, 4)
    gemm_gates_kernel<<<grid, 256>>>(input, h, P);

    const int n = (int)(GATE_ELEMS);
    lstm_epilogue_kernel<<<(n + 255) / 256, 256>>>(
        c, b_ii, b_ih, b_fi, b_fh, b_gi, b_gh, b_oi, b_oh, out);
}

// round 8
// speedup vs baseline: 3.6695x; 3.6695x over previous
#include <cuda_runtime.h>
#include <cuda_bf16.h>
#include <math.h>
#include <stdint.h>

// LSTM cell via warp-level bf16 mma.sync (base PTX ISA — safe for plain sm_103 target).
// Split-bf16: logical K = 6144 = Ahi*Whi + Alo*Whi + Ahi*Wlo (lo*lo dropped),
// dedup'd to 64 stored K-chunks (of 64 bf16) per operand.
// Packed operands are pre-SW128-swizzled so stage loads are identity 16B copies.

#define BATCH_N 4096
#define HID_N   1024
#define GATE_ELEMS ((size_t)BATCH_N * HID_N)

#define NCHUNK  96          // logical K chunks of 64 bf16
#define ACHUNKS 64
#define BCHUNKS 64
#define TILE_M  128
#define TILE_N  128         // packed gate-rows r = 4*j + gate
#define NT_M    32
#define NT_N    32
#define A_BLK   16384       // 128 rows * 128B
#define B_BLK   16384
#define STAGE_BYTES (A_BLK + B_BLK)   // 32 KB
#define NSTAGE  3
#define SMEM_TOTAL (NSTAGE * STAGE_BYTES)   // 98304

__device__ __align__(1024) unsigned char g_Apack[(size_t)NT_M * ACHUNKS * A_BLK];  // 32 MB
__device__ __align__(1024) unsigned char g_Bpack[(size_t)NT_N * BCHUNKS * B_BLK];  // 32 MB
__device__ float g_bias[4096];

// ---------------------------------------------------------------- PTX helpers (base ISA)
__device__ __forceinline__ uint32_t smem_u32(const void* p) {
    uint32_t a;
    asm("{ .reg .u64 t; cvta.to.shared.u64 t, %1; cvt.u32.u64 %0, t; }" : "=r"(a) : "l"(p));
    return a;
}
__device__ __forceinline__ void cp_async16(uint32_t dst, const void* src) {
    asm volatile("cp.async.cg.shared.global [%0], [%1], 16;" :: "r"(dst), "l"(src) : "memory");
}
__device__ __forceinline__ void cp_commit() {
    asm volatile("cp.async.commit_group;" ::: "memory");
}
template <int N>
__device__ __forceinline__ void cp_wait() {
    asm volatile("cp.async.wait_group %0;" :: "n"(N) : "memory");
}
__device__ __forceinline__ void ldsm_x4(uint32_t& r0, uint32_t& r1, uint32_t& r2, uint32_t& r3,
                                        uint32_t addr) {
    asm volatile("ldmatrix.sync.aligned.m8n8.x4.shared.b16 {%0,%1,%2,%3}, [%4];"
                 : "=r"(r0), "=r"(r1), "=r"(r2), "=r"(r3) : "r"(addr));
}
__device__ __forceinline__ void mma16816(float& d0, float& d1, float& d2, float& d3,
                                         uint32_t a0, uint32_t a1, uint32_t a2, uint32_t a3,
                                         uint32_t b0, uint32_t b1) {
    asm volatile("mma.sync.aligned.m16n8k16.row.col.f32.bf16.bf16.f32 "
                 "{%0,%1,%2,%3}, {%4,%5,%6,%7}, {%8,%9}, {%0,%1,%2,%3};"
                 : "+f"(d0), "+f"(d1), "+f"(d2), "+f"(d3)
                 : "r"(a0), "r"(a1), "r"(a2), "r"(a3), "r"(b0), "r"(b1));
}
__device__ __forceinline__ uint32_t swz(uint32_t off) { return off ^ ((off >> 3) & 0x70u); }

// logical chunk -> stored chunk
// A logical: [0:2048) hi | [2048:4096) lo | [4096:6144) hi(dup)   stored: [0,4096)
// B logical: [0:2048) hi | [2048:4096) hi(dup) | [4096:6144) lo   stored: hi 0-31, lo 32-63
__device__ __forceinline__ int map_a(int ck) { return (ck < 64) ? ck : ck - 64; }
__device__ __forceinline__ int map_b(int ck) { return (ck < 32) ? ck : ck - 32; }

// ---------------------------------------------------------------- pack kernels

struct LstmPtrs {
    const float* wi[4];
    const float* wh[4];
    const float* bi[4];
    const float* bh[4];
};

// A stored chunks 0..63 over k in [0,4096):
// [0:1024) hi(input) | [1024:2048) hi(h) | [2048:3072) lo(input) | [3072:4096) lo(h)
__global__ __launch_bounds__(256)
void pack_a_kernel(const float* __restrict__ input, const float* __restrict__ hst)
{
    uint32_t u = blockIdx.x * 256u + threadIdx.x;     // one 16B unit (8 bf16)
    uint32_t tile_m = u / (ACHUNKS * 1024u);
    uint32_t rem = u % (ACHUNKS * 1024u);
    uint32_t ck = rem / 1024u;
    uint32_t w = rem % 1024u;
    uint32_t i = w >> 3;
    uint32_t kq = w & 7u;
    uint32_t row = tile_m * TILE_M + i;
    uint32_t k = ck * 64u + kq * 8u;        // [0, 4096)
    uint32_t seg = k >> 11;                 // 0: hi, 1: lo
    uint32_t kin = k & 2047u;
    const float* src = (kin < 1024u) ? input : hst;
    uint32_t col = kin & 1023u;

    const float4* sp = reinterpret_cast<const float4*>(src + (size_t)row * HID_N + col);
    float4 v0 = sp[0], v1 = sp[1];
    float vals[8] = {v0.x, v0.y, v0.z, v0.w, v1.x, v1.y, v1.z, v1.w};
    __align__(16) __nv_bfloat16 ob[8];
    bool want_lo = (seg == 1u);
#pragma unroll
    for (int t = 0; t < 8; t++) {
        __nv_bfloat16 hi = __float2bfloat16_rn(vals[t]);
        ob[t] = want_lo ? __float2bfloat16_rn(vals[t] - __bfloat162float(hi)) : hi;
    }
    uint32_t off = i * 128u + kq * 16u;
    *reinterpret_cast<uint4*>(g_Apack + (size_t)(tile_m * ACHUNKS + ck) * A_BLK + swz(off)) =
        *reinterpret_cast<uint4*>(ob);
}

// B tiles of 128 packed rows r = 4*j + gate (0=i,1=f,2=g,3=o), n-major (row=n, 64 k cols).
// stored slots 0..31 = hi (k in [0,2048): even 1024-seg = Wi, odd = Wh),
// slots 32..63 = lo (klog in [4096,6144)).
__global__ __launch_bounds__(256)
void pack_b_kernel(LstmPtrs P)
{
    uint32_t u = blockIdx.x * 256u + threadIdx.x;
    uint32_t tile_n = u / (BCHUNKS * 1024u);
    uint32_t rem = u % (BCHUNKS * 1024u);
    uint32_t cks = rem / 1024u;             // storage slot
    uint32_t w = rem % 1024u;
    uint32_t i = w >> 3;                    // row in tile (0..127)
    uint32_t kq = w & 7u;
    uint32_t r = tile_n * TILE_N + i;
    uint32_t j = r >> 2;
    uint32_t g = r & 3u;
    uint32_t klog = ((cks < 32u) ? cks : cks + 32u) * 64u + kq * 8u;
    uint32_t seg6 = klog >> 10;             // 0,1 hi(Wi,Wh); 4,5 lo(Wi,Wh)
    uint32_t col = klog & 1023u;
    const float* src = (seg6 & 1u) ? P.wh[g] : P.wi[g];
    bool want_lo = (seg6 >= 4u);

    const float4* sp = reinterpret_cast<const float4*>(src + (size_t)j * HID_N + col);
    float4 v0 = sp[0], v1 = sp[1];
    float vals[8] = {v0.x, v0.y, v0.z, v0.w, v1.x, v1.y, v1.z, v1.w};
    __align__(16) __nv_bfloat16 ob[8];
#pragma unroll
    for (int t = 0; t < 8; t++) {
        __nv_bfloat16 hi = __float2bfloat16_rn(vals[t]);
        ob[t] = want_lo ? __float2bfloat16_rn(vals[t] - __bfloat162float(hi)) : hi;
    }
    uint32_t off = i * 128u + kq * 16u;
    *reinterpret_cast<uint4*>(g_Bpack + (size_t)(tile_n * BCHUNKS + cks) * B_BLK + swz(off)) =
        *reinterpret_cast<uint4*>(ob);

    // combined biases: one per packed row
    if (u < 4096u) {
        uint32_t rr = u, jj = rr >> 2, gg = rr & 3u;
        g_bias[rr] = P.bi[gg][jj] + P.bh[gg][jj];
    }
}

// ---------------------------------------------------------------- GEMM + fused LSTM epilogue

__device__ __forceinline__ void load_stage(uint32_t sdst, const unsigned char* aSrc,
                                           const unsigned char* bSrc, int tid)
{
#pragma unroll
    for (int i = 0; i < 4; i++)
        cp_async16(sdst + tid * 16 + i * 4096, aSrc + tid * 16 + i * 4096);
#pragma unroll
    for (int i = 0; i < 4; i++)
        cp_async16(sdst + A_BLK + tid * 16 + i * 4096, bSrc + tid * 16 + i * 4096);
}

__global__ __launch_bounds__(256, 2)
void lstm_mma_kernel(const float* __restrict__ cprev, float* __restrict__ out)
{
    extern __shared__ __align__(1024) unsigned char smem[];
    const uint32_t sb = smem_u32(smem);
    const int tid = threadIdx.x;
    const int warp = tid >> 5, lane = tid & 31;
    const int wm = warp & 3, wn = warp >> 2;      // 4 (M) x 2 (N) warps
    const int m_warp = wm * 32, n_warp = wn * 64;
    const int tile_n = blockIdx.x, tile_m = blockIdx.y;

    const unsigned char* aBase = g_Apack + (size_t)tile_m * ACHUNKS * A_BLK;
    const unsigned char* bBase = g_Bpack + (size_t)tile_n * BCHUNKS * B_BLK;

    float acc[2][8][4];
#pragma unroll
    for (int mt = 0; mt < 2; mt++)
#pragma unroll
        for (int nt = 0; nt < 8; nt++)
#pragma unroll
            for (int e = 0; e < 4; e++) acc[mt][nt][e] = 0.0f;

    // prefetch stages 0,1
    load_stage(sb, aBase + (size_t)map_a(0) * A_BLK, bBase + (size_t)map_b(0) * B_BLK, tid);
    cp_commit();
    load_stage(sb + STAGE_BYTES, aBase + (size_t)map_a(1) * A_BLK,
               bBase + (size_t)map_b(1) * B_BLK, tid);
    cp_commit();

    // ldmatrix lane addressing
    const uint32_t a_row = (uint32_t)(lane & 15);          // 0..15
    const uint32_t a_half = (uint32_t)(lane >> 4);         // 0/1 -> k byte-half
    const uint32_t b_row8 = (uint32_t)(lane & 7);          // row within 8x8
    const uint32_t b_khalf = (uint32_t)((lane >> 3) & 1);  // k 8-element half
    const uint32_t b_tsel = (uint32_t)(lane >> 4);         // which n-tile of the pair

    for (int ck = 0; ck < NCHUNK; ck++) {
        if (ck < NCHUNK - 2) cp_wait<1>(); else cp_wait<0>();
        __syncthreads();

        const uint32_t sA = sb + (uint32_t)(ck % NSTAGE) * STAGE_BYTES;
        const uint32_t sB = sA + A_BLK;

#pragma unroll
        for (int ks = 0; ks < 4; ks++) {
            const uint32_t kb = (uint32_t)ks * 32u;        // 16 k-elems = 32 bytes
            // A fragments: 2 m-tiles of 16x16
            uint32_t a[2][4];
#pragma unroll
            for (int mt = 0; mt < 2; mt++) {
                uint32_t off = (uint32_t)(m_warp + mt * 16 + a_row) * 128u + kb + a_half * 16u;
                ldsm_x4(a[mt][0], a[mt][1], a[mt][2], a[mt][3], sA + swz(off));
            }
            // B fragments: n-major rows -> NON-trans ldmatrix.
            // One x4 covers n-tiles (2p, 2p+1) x k-halves:
            //   lanes 0-7:   tile 2p rows,   k-lo  -> r0 = b0(2p)
            //   lanes 8-15:  tile 2p rows,   k-hi  -> r1 = b1(2p)
            //   lanes 16-23: tile 2p+1 rows, k-lo  -> r2 = b0(2p+1)
            //   lanes 24-31: tile 2p+1 rows, k-hi  -> r3 = b1(2p+1)
            uint32_t b[8][2];
#pragma unroll
            for (int p = 0; p < 4; p++) {
                uint32_t nrow = (uint32_t)n_warp + (uint32_t)p * 16u + b_tsel * 8u + b_row8;
                uint32_t off = nrow * 128u + kb + b_khalf * 16u;
                uint32_t r0, r1, r2, r3;
                ldsm_x4(r0, r1, r2, r3, sB + swz(off));
                b[p * 2 + 0][0] = r0; b[p * 2 + 0][1] = r1;
                b[p * 2 + 1][0] = r2; b[p * 2 + 1][1] = r3;
            }
#pragma unroll
            for (int mt = 0; mt < 2; mt++)
#pragma unroll
                for (int nt = 0; nt < 8; nt++)
                    mma16816(acc[mt][nt][0], acc[mt][nt][1], acc[mt][nt][2], acc[mt][nt][3],
                             a[mt][0], a[mt][1], a[mt][2], a[mt][3],
                             b[nt][0], b[nt][1]);
        }

        __syncthreads();
        const int nk = ck + 2;
        if (nk < NCHUNK) {
            const uint32_t sN = sb + (uint32_t)(nk % NSTAGE) * STAGE_BYTES;
            load_stage(sN, aBase + (size_t)map_a(nk) * A_BLK,
                       bBase + (size_t)map_b(nk) * B_BLK, tid);
            cp_commit();
        }
    }

    // ---------------- fused LSTM epilogue ----------------
    // D frag: d0,d1 = row lane/4, cols 2q,2q+1; d2,d3 = row+8 (q = lane%4).
    // Packed cols: 4j+{0,1,2,3} = {i,f,g,o}. Even lane holds (i,f), odd holds (g,o)
    // for the same j. shfl_xor(1): even sends its row+8 (i,f), odd sends its row (g,o);
    // even finalizes row, odd finalizes row+8.
    const int q = lane & 3;
    const int par = lane & 1;
    const int row_base = tile_m * TILE_M + m_warp + (lane >> 2);

#pragma unroll
    for (int mt = 0; mt < 2; mt++) {
#pragma unroll
        for (int nt = 0; nt < 8; nt++) {
            float d0 = acc[mt][nt][0], d1 = acc[mt][nt][1];
            float d2 = acc[mt][nt][2], d3 = acc[mt][nt][3];
            float s0 = par ? d0 : d2;
            float s1 = par ? d1 : d3;
            float r0 = __shfl_xor_sync(0xffffffffu, s0, 1);
            float r1 = __shfl_xor_sync(0xffffffffu, s1, 1);

            float xi, xf, xg, xo;
            if (!par) { xi = d0; xf = d1; xg = r0; xo = r1; }
            else      { xi = r0; xf = r1; xg = d2; xo = d3; }

            const int gcol = tile_n * TILE_N + n_warp + nt * 8 + q * 2;
            const int C = gcol & ~3;
            const int j = C >> 2;
            const int row = row_base + mt * 16 + (par ? 8 : 0);

            xi += g_bias[C + 0];
            xf += g_bias[C + 1];
            xg += g_bias[C + 2];
            xo += g_bias[C + 3];

            float gi = 1.0f / (1.0f + expf(-xi));
            float gf = 1.0f / (1.0f + expf(-xf));
            float gg = tanhf(xg);
            float go = 1.0f / (1.0f + expf(-xo));
            float cn = gf * cprev[(size_t)row * HID_N + j] + gi * gg;
            float hn = go * tanhf(cn);

            out[(size_t)row * HID_N + j] = hn;
            out[GATE_ELEMS + (size_t)row * HID_N + j] = cn;
        }
    }
}

// ---------------------------------------------------------------- launch

extern "C" void kernel_launch(void* const* d_in, const int* in_sizes, int n_in,
                              void* d_out, int out_size)
{
    const float* input = (const float*)d_in[0];
    const float* h     = (const float*)d_in[1];
    const float* c     = (const float*)d_in[2];

    LstmPtrs P;
    P.wi[0] = (const float*)d_in[3];  P.bi[0] = (const float*)d_in[4];
    P.wh[0] = (const float*)d_in[5];  P.bh[0] = (const float*)d_in[6];
    P.wi[1] = (const float*)d_in[7];  P.bi[1] = (const float*)d_in[8];
    P.wh[1] = (const float*)d_in[9];  P.bh[1] = (const float*)d_in[10];
    P.wi[2] = (const float*)d_in[11]; P.bi[2] = (const float*)d_in[12];
    P.wh[2] = (const float*)d_in[13]; P.bh[2] = (const float*)d_in[14];
    P.wi[3] = (const float*)d_in[15]; P.bi[3] = (const float*)d_in[16];
    P.wh[3] = (const float*)d_in[17]; P.bh[3] = (const float*)d_in[18];

    float* out = (float*)d_out;

    pack_a_kernel<<<8192, 256>>>(input, h);
    pack_b_kernel<<<8192, 256>>>(P);

    cudaFuncSetAttribute(lstm_mma_kernel,
                         cudaFuncAttributeMaxDynamicSharedMemorySize, SMEM_TOTAL);
    dim3 grid(NT_N, NT_M);     // (32, 32)
    lstm_mma_kernel<<<grid, 256, SMEM_TOTAL>>>(c, out);
}